// round 1
// baseline (speedup 1.0000x reference)
#include <cuda_runtime.h>
#include <cstddef>

// Problem constants
#define BB 4
#define HH 256
#define WW 256
#define HWPLANE (HH * WW)
#define NF 64
#define KK 15
#define KK2 (KK * KK)   // 225

// -------- scratch (device globals; no alloc allowed) --------
__device__ float g_feat0[BB * NF * HWPLANE];          // 64 MB
__device__ float g_feat1[BB * NF * HWPLANE];          // 64 MB
__device__ float g_core [BB * KK2 * HWPLANE];         // 236 MB

// -------- f32x2 helpers --------
typedef unsigned long long u64;

__device__ __forceinline__ u64 pack2(float lo, float hi) {
    u64 r;
    asm("mov.b64 %0, {%1, %2};" : "=l"(r) : "f"(lo), "f"(hi));
    return r;
}
__device__ __forceinline__ void unpack2(u64 v, float& lo, float& hi) {
    asm("mov.b64 {%0, %1}, %2;" : "=f"(lo), "=f"(hi) : "l"(v));
}
__device__ __forceinline__ void fma2(u64& acc, u64 a, u64 b) {
    asm("fma.rn.f32x2 %0, %1, %2, %0;" : "+l"(acc) : "l"(a), "l"(b));
}

// ============================================================
// conv3x3 SAME, NCHW, fp32. Tile: 32x32 spatial, 4 out-channels
// per block, 256 threads (16x16), each thread 2x2 pixels.
// f32x2 packs the two horizontally adjacent pixels.
// ============================================================
template<int IC, bool RELU, bool RESID>
__global__ __launch_bounds__(256)
void conv3x3_k(const float* __restrict__ in,
               const float* __restrict__ wgt,
               const float* __restrict__ bias,
               const float* __restrict__ resid,
               float* __restrict__ out,
               int OC, int ocGroups)
{
    __shared__ float  s_in[2][34 * 36];
    __shared__ float2 s_w[IC * 36];        // [ic][ocl(4)][tap(9)], duplicated {w,w}

    const int tid = threadIdx.x;
    const int tx = tid & 15;
    const int ty = tid >> 4;
    const int tile_x = blockIdx.x * 32;
    const int tile_y = blockIdx.y * 32;
    const int zb = blockIdx.z;
    const int b   = zb / ocGroups;
    const int g   = zb - b * ocGroups;
    const int oc0 = g * 4;

    // ---- weights into smem (duplicated pairs) ----
    for (int i = tid; i < IC * 36; i += 256) {
        int ic  = i / 36;
        int r   = i - ic * 36;
        int ocl = r / 9;
        int tap = r - ocl * 9;
        int oc  = oc0 + ocl;
        float v = (oc < OC) ? wgt[((size_t)oc * IC + ic) * 9 + tap] : 0.0f;
        s_w[i] = make_float2(v, v);
    }

    float bz[4];
#pragma unroll
    for (int o = 0; o < 4; o++)
        bz[o] = (oc0 + o < OC) ? bias[oc0 + o] : 0.0f;

    const float* inb = in + (size_t)b * IC * HWPLANE;

    // ---- load ic = 0 tile ----
    {
        const float* plane = inb;
        for (int i = tid; i < 34 * 34; i += 256) {
            int r = i / 34, c = i - r * 34;
            int gy = tile_y + r - 1, gx = tile_x + c - 1;
            float v = 0.0f;
            if (gy >= 0 && gy < HH && gx >= 0 && gx < WW) v = plane[gy * WW + gx];
            s_in[0][r * 36 + c] = v;
        }
    }
    __syncthreads();

    u64 acc[4][2];
#pragma unroll
    for (int o = 0; o < 4; o++) {
        u64 bb2 = pack2(bz[o], bz[o]);
        acc[o][0] = bb2;
        acc[o][1] = bb2;
    }

    int buf = 0;
    for (int ic = 0; ic < IC; ++ic) {
        // prefetch next input channel into the other buffer
        if (ic + 1 < IC) {
            const float* plane = inb + (size_t)(ic + 1) * HWPLANE;
            float* dst = s_in[buf ^ 1];
            for (int i = tid; i < 34 * 34; i += 256) {
                int r = i / 34, c = i - r * 34;
                int gy = tile_y + r - 1, gx = tile_x + c - 1;
                float v = 0.0f;
                if (gy >= 0 && gy < HH && gx >= 0 && gx < WW) v = plane[gy * WW + gx];
                dst[r * 36 + c] = v;
            }
        }

        // compute on current buffer
        const float* S = s_in[buf];
        float v[4][4];
#pragma unroll
        for (int r = 0; r < 4; r++)
#pragma unroll
            for (int m = 0; m < 4; m++)
                v[r][m] = S[(2 * ty + r) * 36 + (2 * tx + m)];

        u64 p[4][3];
#pragma unroll
        for (int r = 0; r < 4; r++)
#pragma unroll
            for (int kj = 0; kj < 3; kj++)
                p[r][kj] = pack2(v[r][kj], v[r][kj + 1]);

        const float2* Wc = &s_w[ic * 36];
#pragma unroll
        for (int ocl = 0; ocl < 4; ocl++) {
#pragma unroll
            for (int ki = 0; ki < 3; ki++) {
#pragma unroll
                for (int kj = 0; kj < 3; kj++) {
                    u64 w2 = *reinterpret_cast<const u64*>(&Wc[ocl * 9 + ki * 3 + kj]);
                    fma2(acc[ocl][0], p[ki][kj],     w2);
                    fma2(acc[ocl][1], p[ki + 1][kj], w2);
                }
            }
        }
        __syncthreads();
        buf ^= 1;
    }

    // ---- store ----
    const int x0 = tile_x + 2 * tx;
#pragma unroll
    for (int ocl = 0; ocl < 4; ocl++) {
        int oc = oc0 + ocl;
        if (oc >= OC) break;
        size_t base = ((size_t)b * OC + oc) * HWPLANE;
#pragma unroll
        for (int dy = 0; dy < 2; dy++) {
            int y = tile_y + 2 * ty + dy;
            float f0, f1;
            unpack2(acc[ocl][dy], f0, f1);
            size_t idx = base + (size_t)y * WW + x0;
            if (RELU) { f0 = fmaxf(f0, 0.0f); f1 = fmaxf(f1, 0.0f); }
            if (RESID) { f0 += resid[idx]; f1 += resid[idx + 1]; }
            out[idx]     = f0;
            out[idx + 1] = f1;
        }
    }
}

// ============================================================
// kernel_conv: per-pixel softmax(|core|) over 225 taps, then
// 15x15 dynamic filtering of data. One pixel per thread,
// 16x16 pixel tile per block, data patch staged in smem.
// No max-subtraction: |core| is bounded far below exp overflow,
// and softmax is shift-invariant.
// ============================================================
__global__ __launch_bounds__(256)
void kpn_apply_k(const float* __restrict__ core,
                 const float* __restrict__ data,
                 float* __restrict__ pred)
{
    __shared__ float s_data[3][30][32];   // 16+14 halo rows/cols, col-padded

    const int tid = threadIdx.x;
    const int lx = tid & 15;
    const int ly = tid >> 4;
    const int tile_x = blockIdx.x * 16;
    const int tile_y = blockIdx.y * 16;
    const int b = blockIdx.z;

    // stage data patch (zero padded)
    for (int i = tid; i < 3 * 30 * 30; i += 256) {
        int c = i / 900;
        int r = (i - c * 900) / 30;
        int col = i - c * 900 - r * 30;
        int gy = tile_y - 7 + r;
        int gx = tile_x - 7 + col;
        float v = 0.0f;
        if (gy >= 0 && gy < HH && gx >= 0 && gx < WW)
            v = data[((size_t)b * 3 + c) * HWPLANE + gy * WW + gx];
        s_data[c][r][col] = v;
    }
    __syncthreads();

    const int y = tile_y + ly;
    const int x = tile_x + lx;
    const float* cb = core + (size_t)b * KK2 * HWPLANE + (size_t)y * WW + x;

    float S = 0.0f, P0 = 0.0f, P1 = 0.0f, P2 = 0.0f;

    for (int ki = 0; ki < KK; ki++) {
#pragma unroll
        for (int kj = 0; kj < KK; kj++) {
            float c = cb[(size_t)(ki * KK + kj) * HWPLANE];
            float w = __expf(fabsf(c));
            S += w;
            P0 += w * s_data[0][ly + ki][lx + kj];
            P1 += w * s_data[1][ly + ki][lx + kj];
            P2 += w * s_data[2][ly + ki][lx + kj];
        }
    }

    float inv = 1.0f / S;
    size_t o = (size_t)b * 3 * HWPLANE + (size_t)y * WW + x;
    pred[o]                = P0 * inv;
    pred[o + HWPLANE]      = P1 * inv;
    pred[o + 2 * HWPLANE]  = P2 * inv;
}

// ============================================================
// launch
// ============================================================
static float* sym_addr(const void* s)
{
    void* p = nullptr;
    cudaGetSymbolAddress(&p, s);
    return (float*)p;
}

extern "C" void kernel_launch(void* const* d_in, const int* in_sizes, int n_in,
                              void* d_out, int out_size)
{
    const float* dwe     = (const float*)d_in[0];   // data_with_est [4,6,256,256]
    const float* data    = (const float*)d_in[1];   // data          [4,3,256,256]
    const float* w_first = (const float*)d_in[2];
    const float* b_first = (const float*)d_in[3];
    const float* w1a = (const float*)d_in[4];
    const float* b1a = (const float*)d_in[5];
    const float* w1b = (const float*)d_in[6];
    const float* b1b = (const float*)d_in[7];
    const float* w2a = (const float*)d_in[8];
    const float* b2a = (const float*)d_in[9];
    const float* w2b = (const float*)d_in[10];
    const float* b2b = (const float*)d_in[11];
    const float* w3a = (const float*)d_in[12];
    const float* b3a = (const float*)d_in[13];
    const float* w3b = (const float*)d_in[14];
    const float* b3b = (const float*)d_in[15];
    const float* w_out = (const float*)d_in[16];
    const float* b_out = (const float*)d_in[17];

    float* f0   = sym_addr(g_feat0);
    float* f1   = sym_addr(g_feat1);
    float* core = sym_addr(g_core);

    dim3 blk(256);
    dim3 grid64(WW / 32, HH / 32, BB * (NF / 4));       // 8,8,64
    const int ocGroupsOut = (KK2 + 3) / 4;              // 57
    dim3 gridOut(WW / 32, HH / 32, BB * ocGroupsOut);   // 8,8,228

    // first conv: 6 -> 64
    conv3x3_k<6, false, false><<<grid64, blk>>>(dwe, w_first, b_first, nullptr, f0, NF, NF / 4);

    // res block 1
    conv3x3_k<64, true,  false><<<grid64, blk>>>(f0, w1a, b1a, nullptr, f1, NF, NF / 4);
    conv3x3_k<64, false, true ><<<grid64, blk>>>(f1, w1b, b1b, f0,      f0, NF, NF / 4);
    // res block 2
    conv3x3_k<64, true,  false><<<grid64, blk>>>(f0, w2a, b2a, nullptr, f1, NF, NF / 4);
    conv3x3_k<64, false, true ><<<grid64, blk>>>(f1, w2b, b2b, f0,      f0, NF, NF / 4);
    // res block 3
    conv3x3_k<64, true,  false><<<grid64, blk>>>(f0, w3a, b3a, nullptr, f1, NF, NF / 4);
    conv3x3_k<64, false, true ><<<grid64, blk>>>(f1, w3b, b3b, f0,      f0, NF, NF / 4);

    // out conv: 64 -> 225
    conv3x3_k<64, false, false><<<gridOut, blk>>>(f0, w_out, b_out, nullptr, core, KK2, ocGroupsOut);

    // output[0] = data (passthrough)
    cudaMemcpyAsync(d_out, data, (size_t)BB * 3 * HWPLANE * sizeof(float),
                    cudaMemcpyDeviceToDevice, 0);

    // output[1] = pred
    dim3 gridK(WW / 16, HH / 16, BB);
    kpn_apply_k<<<gridK, blk>>>(core, data, (float*)d_out + (size_t)BB * 3 * HWPLANE);
}

// round 2
// speedup vs baseline: 1.0004x; 1.0004x over previous
#include <cuda_runtime.h>
#include <cstddef>

// Problem constants
#define BB 4
#define HH 256
#define WW 256
#define HWPLANE (HH * WW)
#define NF 64
#define KK 15
#define KK2 (KK * KK)   // 225

// -------- scratch (device globals; no alloc allowed) --------
__device__ float g_feat0[BB * NF * HWPLANE];          // 64 MB
__device__ float g_feat1[BB * NF * HWPLANE];          // 64 MB
__device__ float g_core [BB * KK2 * HWPLANE];         // 236 MB

// -------- f32x2 helpers --------
typedef unsigned long long u64;

__device__ __forceinline__ u64 pack2(float lo, float hi) {
    u64 r;
    asm("mov.b64 %0, {%1, %2};" : "=l"(r) : "f"(lo), "f"(hi));
    return r;
}
__device__ __forceinline__ void unpack2(u64 v, float& lo, float& hi) {
    asm("mov.b64 {%0, %1}, %2;" : "=f"(lo), "=f"(hi) : "l"(v));
}
__device__ __forceinline__ void fma2(u64& acc, u64 a, u64 b) {
    asm("fma.rn.f32x2 %0, %1, %2, %0;" : "+l"(acc) : "l"(a), "l"(b));
}

// ============================================================
// conv3x3 SAME, NCHW, fp32. Tile: 32x32 spatial, 4 out-channels
// per block, 256 threads (16x16), each thread 2x2 pixels.
// f32x2 packs the two horizontally adjacent pixels.
// ============================================================
template<int IC, bool RELU, bool RESID>
__global__ __launch_bounds__(256)
void conv3x3_k(const float* __restrict__ in,
               const float* __restrict__ wgt,
               const float* __restrict__ bias,
               const float* __restrict__ resid,
               float* __restrict__ out,
               int OC, int ocGroups)
{
    __shared__ float  s_in[2][34 * 36];
    __shared__ float2 s_w[IC * 36];        // [ic][ocl(4)][tap(9)], duplicated {w,w}

    const int tid = threadIdx.x;
    const int tx = tid & 15;
    const int ty = tid >> 4;
    const int tile_x = blockIdx.x * 32;
    const int tile_y = blockIdx.y * 32;
    const int zb = blockIdx.z;
    const int b   = zb / ocGroups;
    const int g   = zb - b * ocGroups;
    const int oc0 = g * 4;

    // ---- weights into smem (duplicated pairs) ----
    for (int i = tid; i < IC * 36; i += 256) {
        int ic  = i / 36;
        int r   = i - ic * 36;
        int ocl = r / 9;
        int tap = r - ocl * 9;
        int oc  = oc0 + ocl;
        float v = (oc < OC) ? wgt[((size_t)oc * IC + ic) * 9 + tap] : 0.0f;
        s_w[i] = make_float2(v, v);
    }

    float bz[4];
#pragma unroll
    for (int o = 0; o < 4; o++)
        bz[o] = (oc0 + o < OC) ? bias[oc0 + o] : 0.0f;

    const float* inb = in + (size_t)b * IC * HWPLANE;

    // ---- load ic = 0 tile ----
    {
        const float* plane = inb;
        for (int i = tid; i < 34 * 34; i += 256) {
            int r = i / 34, c = i - r * 34;
            int gy = tile_y + r - 1, gx = tile_x + c - 1;
            float v = 0.0f;
            if (gy >= 0 && gy < HH && gx >= 0 && gx < WW) v = plane[gy * WW + gx];
            s_in[0][r * 36 + c] = v;
        }
    }
    __syncthreads();

    u64 acc[4][2];
#pragma unroll
    for (int o = 0; o < 4; o++) {
        u64 bb2 = pack2(bz[o], bz[o]);
        acc[o][0] = bb2;
        acc[o][1] = bb2;
    }

    int buf = 0;
    for (int ic = 0; ic < IC; ++ic) {
        // prefetch next input channel into the other buffer
        if (ic + 1 < IC) {
            const float* plane = inb + (size_t)(ic + 1) * HWPLANE;
            float* dst = s_in[buf ^ 1];
            for (int i = tid; i < 34 * 34; i += 256) {
                int r = i / 34, c = i - r * 34;
                int gy = tile_y + r - 1, gx = tile_x + c - 1;
                float v = 0.0f;
                if (gy >= 0 && gy < HH && gx >= 0 && gx < WW) v = plane[gy * WW + gx];
                dst[r * 36 + c] = v;
            }
        }

        // compute on current buffer
        const float* S = s_in[buf];
        float v[4][4];
#pragma unroll
        for (int r = 0; r < 4; r++)
#pragma unroll
            for (int m = 0; m < 4; m++)
                v[r][m] = S[(2 * ty + r) * 36 + (2 * tx + m)];

        u64 p[4][3];
#pragma unroll
        for (int r = 0; r < 4; r++)
#pragma unroll
            for (int kj = 0; kj < 3; kj++)
                p[r][kj] = pack2(v[r][kj], v[r][kj + 1]);

        const float2* Wc = &s_w[ic * 36];
#pragma unroll
        for (int ocl = 0; ocl < 4; ocl++) {
#pragma unroll
            for (int ki = 0; ki < 3; ki++) {
#pragma unroll
                for (int kj = 0; kj < 3; kj++) {
                    u64 w2 = *reinterpret_cast<const u64*>(&Wc[ocl * 9 + ki * 3 + kj]);
                    fma2(acc[ocl][0], p[ki][kj],     w2);
                    fma2(acc[ocl][1], p[ki + 1][kj], w2);
                }
            }
        }
        __syncthreads();
        buf ^= 1;
    }

    // ---- store ----
    const int x0 = tile_x + 2 * tx;
#pragma unroll
    for (int ocl = 0; ocl < 4; ocl++) {
        int oc = oc0 + ocl;
        if (oc >= OC) break;
        size_t base = ((size_t)b * OC + oc) * HWPLANE;
#pragma unroll
        for (int dy = 0; dy < 2; dy++) {
            int y = tile_y + 2 * ty + dy;
            float f0, f1;
            unpack2(acc[ocl][dy], f0, f1);
            size_t idx = base + (size_t)y * WW + x0;
            if (RELU) { f0 = fmaxf(f0, 0.0f); f1 = fmaxf(f1, 0.0f); }
            if (RESID) { f0 += resid[idx]; f1 += resid[idx + 1]; }
            out[idx]     = f0;
            out[idx + 1] = f1;
        }
    }
}

// ============================================================
// kernel_conv: per-pixel softmax(|core|) over 225 taps, then
// 15x15 dynamic filtering of data. One pixel per thread,
// 16x16 pixel tile per block, data patch staged in smem.
// No max-subtraction: |core| is bounded far below exp overflow,
// and softmax is shift-invariant.
// ============================================================
__global__ __launch_bounds__(256)
void kpn_apply_k(const float* __restrict__ core,
                 const float* __restrict__ data,
                 float* __restrict__ pred)
{
    __shared__ float s_data[3][30][32];   // 16+14 halo rows/cols, col-padded

    const int tid = threadIdx.x;
    const int lx = tid & 15;
    const int ly = tid >> 4;
    const int tile_x = blockIdx.x * 16;
    const int tile_y = blockIdx.y * 16;
    const int b = blockIdx.z;

    // stage data patch (zero padded)
    for (int i = tid; i < 3 * 30 * 30; i += 256) {
        int c = i / 900;
        int r = (i - c * 900) / 30;
        int col = i - c * 900 - r * 30;
        int gy = tile_y - 7 + r;
        int gx = tile_x - 7 + col;
        float v = 0.0f;
        if (gy >= 0 && gy < HH && gx >= 0 && gx < WW)
            v = data[((size_t)b * 3 + c) * HWPLANE + gy * WW + gx];
        s_data[c][r][col] = v;
    }
    __syncthreads();

    const int y = tile_y + ly;
    const int x = tile_x + lx;
    const float* cb = core + (size_t)b * KK2 * HWPLANE + (size_t)y * WW + x;

    float S = 0.0f, P0 = 0.0f, P1 = 0.0f, P2 = 0.0f;

    for (int ki = 0; ki < KK; ki++) {
#pragma unroll
        for (int kj = 0; kj < KK; kj++) {
            float c = cb[(size_t)(ki * KK + kj) * HWPLANE];
            float w = __expf(fabsf(c));
            S += w;
            P0 += w * s_data[0][ly + ki][lx + kj];
            P1 += w * s_data[1][ly + ki][lx + kj];
            P2 += w * s_data[2][ly + ki][lx + kj];
        }
    }

    float inv = 1.0f / S;
    size_t o = (size_t)b * 3 * HWPLANE + (size_t)y * WW + x;
    pred[o]                = P0 * inv;
    pred[o + HWPLANE]      = P1 * inv;
    pred[o + 2 * HWPLANE]  = P2 * inv;
}

// ============================================================
// launch
// ============================================================
static float* sym_addr(const void* s)
{
    void* p = nullptr;
    cudaGetSymbolAddress(&p, s);
    return (float*)p;
}

extern "C" void kernel_launch(void* const* d_in, const int* in_sizes, int n_in,
                              void* d_out, int out_size)
{
    const float* dwe     = (const float*)d_in[0];   // data_with_est [4,6,256,256]
    const float* data    = (const float*)d_in[1];   // data          [4,3,256,256]
    const float* w_first = (const float*)d_in[2];
    const float* b_first = (const float*)d_in[3];
    const float* w1a = (const float*)d_in[4];
    const float* b1a = (const float*)d_in[5];
    const float* w1b = (const float*)d_in[6];
    const float* b1b = (const float*)d_in[7];
    const float* w2a = (const float*)d_in[8];
    const float* b2a = (const float*)d_in[9];
    const float* w2b = (const float*)d_in[10];
    const float* b2b = (const float*)d_in[11];
    const float* w3a = (const float*)d_in[12];
    const float* b3a = (const float*)d_in[13];
    const float* w3b = (const float*)d_in[14];
    const float* b3b = (const float*)d_in[15];
    const float* w_out = (const float*)d_in[16];
    const float* b_out = (const float*)d_in[17];

    float* f0   = sym_addr(g_feat0);
    float* f1   = sym_addr(g_feat1);
    float* core = sym_addr(g_core);

    dim3 blk(256);
    dim3 grid64(WW / 32, HH / 32, BB * (NF / 4));       // 8,8,64
    const int ocGroupsOut = (KK2 + 3) / 4;              // 57
    dim3 gridOut(WW / 32, HH / 32, BB * ocGroupsOut);   // 8,8,228

    // first conv: 6 -> 64
    conv3x3_k<6, false, false><<<grid64, blk>>>(dwe, w_first, b_first, nullptr, f0, NF, NF / 4);

    // res block 1
    conv3x3_k<64, true,  false><<<grid64, blk>>>(f0, w1a, b1a, nullptr, f1, NF, NF / 4);
    conv3x3_k<64, false, true ><<<grid64, blk>>>(f1, w1b, b1b, f0,      f0, NF, NF / 4);
    // res block 2
    conv3x3_k<64, true,  false><<<grid64, blk>>>(f0, w2a, b2a, nullptr, f1, NF, NF / 4);
    conv3x3_k<64, false, true ><<<grid64, blk>>>(f1, w2b, b2b, f0,      f0, NF, NF / 4);
    // res block 3
    conv3x3_k<64, true,  false><<<grid64, blk>>>(f0, w3a, b3a, nullptr, f1, NF, NF / 4);
    conv3x3_k<64, false, true ><<<grid64, blk>>>(f1, w3b, b3b, f0,      f0, NF, NF / 4);

    // out conv: 64 -> 225
    conv3x3_k<64, false, false><<<gridOut, blk>>>(f0, w_out, b_out, nullptr, core, KK2, ocGroupsOut);

    // output[0] = data (passthrough)
    cudaMemcpyAsync(d_out, data, (size_t)BB * 3 * HWPLANE * sizeof(float),
                    cudaMemcpyDeviceToDevice, 0);

    // output[1] = pred
    dim3 gridK(WW / 16, HH / 16, BB);
    kpn_apply_k<<<gridK, blk>>>(core, data, (float*)d_out + (size_t)BB * 3 * HWPLANE);
}

// round 3
// speedup vs baseline: 1.3059x; 1.3054x over previous
#include <cuda_runtime.h>
#include <cstddef>

// Problem constants
#define BB 4
#define HH 256
#define WW 256
#define HWPLANE (HH * WW)
#define NF 64
#define KK 15
#define KK2 (KK * KK)   // 225

// -------- scratch (device globals; no alloc allowed) --------
__device__ float g_feat0[BB * NF * HWPLANE];          // 64 MB
__device__ float g_feat1[BB * NF * HWPLANE];          // 64 MB
__device__ float g_core [BB * KK2 * HWPLANE];         // 236 MB

// -------- f32x2 helpers --------
typedef unsigned long long u64;

__device__ __forceinline__ u64 pack2(float lo, float hi) {
    u64 r;
    asm("mov.b64 %0, {%1, %2};" : "=l"(r) : "f"(lo), "f"(hi));
    return r;
}
__device__ __forceinline__ void unpack2(u64 v, float& lo, float& hi) {
    asm("mov.b64 {%0, %1}, %2;" : "=f"(lo), "=f"(hi) : "l"(v));
}
__device__ __forceinline__ void fma2(u64& acc, u64 a, u64 b) {
    asm("fma.rn.f32x2 %0, %1, %2, %0;" : "+l"(acc) : "l"(a), "l"(b));
}

// ============================================================
// conv3x3 SAME, NCHW, fp32.
// Tile: 32x32 spatial, 4 out-channels per block, 256 threads.
// Thread tile: 2 px wide (f32x2) x 4 px tall x 4 oc = 32 outputs.
// Prefetch addressing hoisted out of the ic loop; next-channel
// LDGs issued before compute so latency hides under FMAs.
// ============================================================
template<int IC, bool RELU, bool RESID>
__global__ __launch_bounds__(256)
void conv3x3_k(const float* __restrict__ in,
               const float* __restrict__ wgt,
               const float* __restrict__ bias,
               const float* __restrict__ resid,
               float* __restrict__ out,
               int OC, int ocGroups)
{
    __shared__ float  s_in[2][34 * 36];
    __shared__ float2 s_w[IC * 36];        // [ic][ocl(4)][tap(9)], duplicated {w,w}

    const int tid = threadIdx.x;
    const int tx = tid & 15;               // 16 -> 32 px wide (2 each)
    const int ty = tid >> 4;               // 16 -> but only 8 rows of 4... see below
    // Remap: we need 16 x-threads * 8 y-threads = 128? No: use tx 0..15, ty 0..15
    // with 4-tall thread tile we need ty in 0..7 -> use 16x16 grid but ty>>1 ... simpler:
    // tx = tid & 15 (0..15), tyy = tid >> 4 (0..15). Tile is 32 wide x 32 tall:
    // x-span: 16 threads * 2 px = 32. y-span: need 8 groups of 4 px.
    // So use tyy in 0..7 and give each thread TWO oc-pairs? Instead: 16 y-threads,
    // each 2 rows... Simplest consistent mapping: 256 threads = 16(tx) x 16(tyy),
    // thread tile = 2 px wide x 2 px tall x 4 oc, PLUS a second 2-row band.
    // To keep the 4-row accumulator design: tx 0..15, ty8 = tid >> 5 (0..7),
    // and the remaining bit widens x: txw = (tid & 31) -> 32 threads * 1? 
    // Clean solution: tx5 = tid & 31 (0..31, 1 f32x2 pair each? no)
    // Final mapping (used below): tX = tid & 15 (2px), tY = (tid >> 4) & 7 (4px),
    // half = tid >> 7 (0/1) splits the 4 oc into 2+2.
    const int tX   = tid & 15;             // 0..15 -> x pairs
    const int tY   = (tid >> 4) & 7;       // 0..7  -> 4-row bands (32 rows)
    const int half = tid >> 7;             // 0..1  -> oc pair group

    const int tile_x = blockIdx.x * 32;
    const int tile_y = blockIdx.y * 32;
    const int zb = blockIdx.z;
    const int b   = zb / ocGroups;
    const int g   = zb - b * ocGroups;
    const int oc0 = g * 4;
    const int ocA = oc0 + half * 2;        // this thread's 2 ocs: ocA, ocA+1

    // ---- weights into smem (duplicated pairs) ----
    for (int i = tid; i < IC * 36; i += 256) {
        int ic  = i / 36;
        int r   = i - ic * 36;
        int ocl = r / 9;
        int tap = r - ocl * 9;
        int oc  = oc0 + ocl;
        float v = (oc < OC) ? wgt[((size_t)oc * IC + ic) * 9 + tap] : 0.0f;
        s_w[i] = make_float2(v, v);
    }

    float bz[2];
#pragma unroll
    for (int o = 0; o < 2; o++)
        bz[o] = (ocA + o < OC) ? bias[ocA + o] : 0.0f;

    const float* inb = in + (size_t)b * IC * HWPLANE;

    // ---- hoisted prefetch addressing (34x34 halo, 5 elems/thread) ----
    int  pre_s[5], pre_g[5];
    bool pre_ok[5], pre_v[5];
#pragma unroll
    for (int j = 0; j < 5; j++) {
        int i = tid + j * 256;
        bool ok = i < 34 * 34;
        int r = i / 34, c = i - r * 34;
        int gy = tile_y + r - 1, gx = tile_x + c - 1;
        bool v = ok && gy >= 0 && gy < HH && gx >= 0 && gx < WW;
        pre_ok[j] = ok; pre_v[j] = v;
        pre_s[j]  = r * 36 + c;
        pre_g[j]  = gy * WW + gx;
    }

    // ---- load ic = 0 tile ----
    {
        const float* plane = inb;
#pragma unroll
        for (int j = 0; j < 5; j++) {
            float v = pre_v[j] ? plane[pre_g[j]] : 0.0f;
            if (pre_ok[j]) s_in[0][pre_s[j]] = v;
        }
    }
    __syncthreads();

    // acc[ocl(2)][row(4)]
    u64 acc[2][4];
#pragma unroll
    for (int o = 0; o < 2; o++) {
        u64 bb2 = pack2(bz[o], bz[o]);
#pragma unroll
        for (int r = 0; r < 4; r++) acc[o][r] = bb2;
    }

    int buf = 0;
    for (int ic = 0; ic < IC; ++ic) {
        // issue next-channel loads first (latency hidden under compute)
        float pv[5];
        const bool more = (ic + 1 < IC);
        if (more) {
            const float* plane = inb + (size_t)(ic + 1) * HWPLANE;
#pragma unroll
            for (int j = 0; j < 5; j++)
                pv[j] = pre_v[j] ? plane[pre_g[j]] : 0.0f;
        }

        // compute on current buffer: 6 input rows of 3 pairs
        const float* S = s_in[buf] + (4 * tY) * 36 + 2 * tX;
        u64 p[6][3];
#pragma unroll
        for (int r = 0; r < 6; r++) {
            const float* row = S + r * 36;
            u64 a = *reinterpret_cast<const u64*>(row);        // (v0,v1)
            u64 bq = *reinterpret_cast<const u64*>(row + 2);   // (v2,v3)
            float a0, a1, b0, b1;
            unpack2(a, a0, a1); unpack2(bq, b0, b1);
            p[r][0] = a;
            p[r][1] = pack2(a1, b0);
            p[r][2] = bq;
        }

        const float2* Wc = &s_w[ic * 36 + half * 18];
#pragma unroll
        for (int ocl = 0; ocl < 2; ocl++) {
#pragma unroll
            for (int ki = 0; ki < 3; ki++) {
#pragma unroll
                for (int kj = 0; kj < 3; kj++) {
                    u64 w2 = *reinterpret_cast<const u64*>(&Wc[ocl * 9 + ki * 3 + kj]);
                    fma2(acc[ocl][0], p[ki][kj],     w2);
                    fma2(acc[ocl][1], p[ki + 1][kj], w2);
                    fma2(acc[ocl][2], p[ki + 2][kj], w2);
                    fma2(acc[ocl][3], p[ki + 3][kj], w2);
                }
            }
        }

        // stage next channel, then sync
        if (more) {
            float* dst = s_in[buf ^ 1];
#pragma unroll
            for (int j = 0; j < 5; j++)
                if (pre_ok[j]) dst[pre_s[j]] = pv[j];
        }
        __syncthreads();
        buf ^= 1;
    }

    // ---- store (float2 = STG.64) ----
    const int x0 = tile_x + 2 * tX;
#pragma unroll
    for (int ocl = 0; ocl < 2; ocl++) {
        int oc = ocA + ocl;
        if (oc >= OC) break;
        size_t base = ((size_t)b * OC + oc) * HWPLANE;
#pragma unroll
        for (int dy = 0; dy < 4; dy++) {
            int y = tile_y + 4 * tY + dy;
            float f0, f1;
            unpack2(acc[ocl][dy], f0, f1);
            size_t idx = base + (size_t)y * WW + x0;
            if (RELU) { f0 = fmaxf(f0, 0.0f); f1 = fmaxf(f1, 0.0f); }
            if (RESID) {
                float2 rv = *reinterpret_cast<const float2*>(resid + idx);
                f0 += rv.x; f1 += rv.y;
            }
            *reinterpret_cast<float2*>(out + idx) = make_float2(f0, f1);
        }
    }
}

// ============================================================
// kernel_conv: per-pixel softmax(|core|) over 225 taps, then
// 15x15 dynamic filtering of data.
// ============================================================
__global__ __launch_bounds__(256)
void kpn_apply_k(const float* __restrict__ core,
                 const float* __restrict__ data,
                 float* __restrict__ pred)
{
    __shared__ float s_data[3][30][32];

    const int tid = threadIdx.x;
    const int lx = tid & 15;
    const int ly = tid >> 4;
    const int tile_x = blockIdx.x * 16;
    const int tile_y = blockIdx.y * 16;
    const int b = blockIdx.z;

    for (int i = tid; i < 3 * 30 * 30; i += 256) {
        int c = i / 900;
        int r = (i - c * 900) / 30;
        int col = i - c * 900 - r * 30;
        int gy = tile_y - 7 + r;
        int gx = tile_x - 7 + col;
        float v = 0.0f;
        if (gy >= 0 && gy < HH && gx >= 0 && gx < WW)
            v = data[((size_t)b * 3 + c) * HWPLANE + gy * WW + gx];
        s_data[c][r][col] = v;
    }
    __syncthreads();

    const int y = tile_y + ly;
    const int x = tile_x + lx;
    const float* cb = core + (size_t)b * KK2 * HWPLANE + (size_t)y * WW + x;

    float S = 0.0f, P0 = 0.0f, P1 = 0.0f, P2 = 0.0f;

    for (int ki = 0; ki < KK; ki++) {
#pragma unroll
        for (int kj = 0; kj < KK; kj++) {
            float c = cb[(size_t)(ki * KK + kj) * HWPLANE];
            float w = __expf(fabsf(c));
            S += w;
            P0 += w * s_data[0][ly + ki][lx + kj];
            P1 += w * s_data[1][ly + ki][lx + kj];
            P2 += w * s_data[2][ly + ki][lx + kj];
        }
    }

    float inv = 1.0f / S;
    size_t o = (size_t)b * 3 * HWPLANE + (size_t)y * WW + x;
    pred[o]                = P0 * inv;
    pred[o + HWPLANE]      = P1 * inv;
    pred[o + 2 * HWPLANE]  = P2 * inv;
}

// ============================================================
// launch
// ============================================================
static float* sym_addr(const void* s)
{
    void* p = nullptr;
    cudaGetSymbolAddress(&p, s);
    return (float*)p;
}

extern "C" void kernel_launch(void* const* d_in, const int* in_sizes, int n_in,
                              void* d_out, int out_size)
{
    const float* dwe     = (const float*)d_in[0];
    const float* data    = (const float*)d_in[1];
    const float* w_first = (const float*)d_in[2];
    const float* b_first = (const float*)d_in[3];
    const float* w1a = (const float*)d_in[4];
    const float* b1a = (const float*)d_in[5];
    const float* w1b = (const float*)d_in[6];
    const float* b1b = (const float*)d_in[7];
    const float* w2a = (const float*)d_in[8];
    const float* b2a = (const float*)d_in[9];
    const float* w2b = (const float*)d_in[10];
    const float* b2b = (const float*)d_in[11];
    const float* w3a = (const float*)d_in[12];
    const float* b3a = (const float*)d_in[13];
    const float* w3b = (const float*)d_in[14];
    const float* b3b = (const float*)d_in[15];
    const float* w_out = (const float*)d_in[16];
    const float* b_out = (const float*)d_in[17];

    float* f0   = sym_addr(g_feat0);
    float* f1   = sym_addr(g_feat1);
    float* core = sym_addr(g_core);

    dim3 blk(256);
    dim3 grid64(WW / 32, HH / 32, BB * (NF / 4));       // 8,8,64
    const int ocGroupsOut = (KK2 + 3) / 4;              // 57
    dim3 gridOut(WW / 32, HH / 32, BB * ocGroupsOut);   // 8,8,228

    conv3x3_k<6, false, false><<<grid64, blk>>>(dwe, w_first, b_first, nullptr, f0, NF, NF / 4);

    conv3x3_k<64, true,  false><<<grid64, blk>>>(f0, w1a, b1a, nullptr, f1, NF, NF / 4);
    conv3x3_k<64, false, true ><<<grid64, blk>>>(f1, w1b, b1b, f0,      f0, NF, NF / 4);
    conv3x3_k<64, true,  false><<<grid64, blk>>>(f0, w2a, b2a, nullptr, f1, NF, NF / 4);
    conv3x3_k<64, false, true ><<<grid64, blk>>>(f1, w2b, b2b, f0,      f0, NF, NF / 4);
    conv3x3_k<64, true,  false><<<grid64, blk>>>(f0, w3a, b3a, nullptr, f1, NF, NF / 4);
    conv3x3_k<64, false, true ><<<grid64, blk>>>(f1, w3b, b3b, f0,      f0, NF, NF / 4);

    conv3x3_k<64, false, false><<<gridOut, blk>>>(f0, w_out, b_out, nullptr, core, KK2, ocGroupsOut);

    cudaMemcpyAsync(d_out, data, (size_t)BB * 3 * HWPLANE * sizeof(float),
                    cudaMemcpyDeviceToDevice, 0);

    dim3 gridK(WW / 16, HH / 16, BB);
    kpn_apply_k<<<gridK, blk>>>(core, data, (float*)d_out + (size_t)BB * 3 * HWPLANE);
}

// round 4
// speedup vs baseline: 1.3438x; 1.0290x over previous
#include <cuda_runtime.h>
#include <cstddef>

#define BB 4
#define HH 256
#define WW 256
#define HWPLANE (HH * WW)
#define NF 64
#define KK 15
#define KK2 (KK * KK)   // 225

__device__ float g_feat0[BB * NF * HWPLANE];
__device__ float g_feat1[BB * NF * HWPLANE];
__device__ float g_core [BB * KK2 * HWPLANE];

typedef unsigned long long u64;

__device__ __forceinline__ u64 pack2(float lo, float hi) {
    u64 r;
    asm("mov.b64 %0, {%1, %2};" : "=l"(r) : "f"(lo), "f"(hi));
    return r;
}
__device__ __forceinline__ void unpack2(u64 v, float& lo, float& hi) {
    asm("mov.b64 {%0, %1}, %2;" : "=f"(lo), "=f"(hi) : "l"(v));
}
__device__ __forceinline__ void fma2(u64& acc, u64 a, u64 b) {
    asm("fma.rn.f32x2 %0, %1, %2, %0;" : "+l"(acc) : "l"(a), "l"(b));
}

// ============================================================
// conv3x3 SAME, NCHW, fp32.
// Block: 256 threads, tile 32 wide x 64 tall, 4 out-channels.
// Thread: 2px (f32x2) x 8 rows x 2 oc = 32 outputs.
// Weights held in REGISTERS per ic (18 LDS.64 broadcast feeding
// 144 FFMA2). Rolling 3-row input window. Halo stored with a
// -1 column shift so all tap pairs are aligned LDS.64.
// ============================================================
template<int IC, bool RELU, bool RESID>
__global__ __launch_bounds__(256, 2)
void conv3x3_k(const float* __restrict__ in,
               const float* __restrict__ wgt,
               const float* __restrict__ bias,
               const float* __restrict__ resid,
               float* __restrict__ out,
               int OC, int ocGroups)
{
    __shared__ float  s_in[2][66 * 36];
    __shared__ float2 s_w[IC * 36];        // [ic][ocl(4)][tap(9)] duplicated {w,w}

    const int tid  = threadIdx.x;
    const int tX   = tid & 15;             // x pair
    const int tY   = (tid >> 4) & 7;       // 8-row band (64 rows)
    const int half = tid >> 7;             // oc pair select

    const int tile_x = blockIdx.x * 32;
    const int tile_y = blockIdx.y * 64;
    const int zb = blockIdx.z;
    const int b   = zb / ocGroups;
    const int g   = zb - b * ocGroups;
    const int oc0 = g * 4;
    const int ocA = oc0 + half * 2;

    // ---- weights to smem (duplicated pairs) ----
    for (int i = tid; i < IC * 36; i += 256) {
        int ic  = i / 36;
        int r   = i - ic * 36;
        int ocl = r / 9;
        int tap = r - ocl * 9;
        int oc  = oc0 + ocl;
        float v = (oc < OC) ? wgt[((size_t)oc * IC + ic) * 9 + tap] : 0.0f;
        s_w[i] = make_float2(v, v);
    }

    float bz[2];
#pragma unroll
    for (int o = 0; o < 2; o++)
        bz[o] = (ocA + o < OC) ? bias[ocA + o] : 0.0f;

    const float* inb = in + (size_t)b * IC * HWPLANE;

    // ---- hoisted halo addressing ----
    // halo: 66 rows (gy = tile_y-1+row), cols gx = tile_x-2 .. tile_x+33
    // loaded as 18 float2 pairs/row. smem col c' = gx - (tile_x-1), c' in 0..34.
    // pair k: v.x -> c'=2k-1 (skip if k==0), v.y -> c'=2k.
    int sy[5], gofs[5];
    unsigned skipx = 0;
#pragma unroll
    for (int j = 0; j < 5; j++) {
        int i = tid + j * 256;
        int row = i / 18, pc = i - row * 18;
        bool slot = (i < 66 * 18);
        int gy = tile_y - 1 + row;
        int gx0 = tile_x - 2 + 2 * pc;
        bool v = slot && gy >= 0 && gy < HH && gx0 >= 0 && gx0 < WW;
        gofs[j] = v ? (gy * WW + gx0) : -1;
        sy[j]   = slot ? (row * 36 + 2 * pc) * 4 : -1;
        if (pc == 0) skipx |= (1u << j);
    }

    // ---- stage ic = 0 ----
    {
        const float* plane = inb;
        float2 pv[5];
#pragma unroll
        for (int j = 0; j < 5; j++)
            pv[j] = (gofs[j] >= 0) ? *reinterpret_cast<const float2*>(plane + gofs[j])
                                   : make_float2(0.0f, 0.0f);
        char* dst = (char*)s_in[0];
#pragma unroll
        for (int j = 0; j < 5; j++) {
            if (sy[j] >= 0) {
                *reinterpret_cast<float*>(dst + sy[j]) = pv[j].y;
                if (!((skipx >> j) & 1))
                    *reinterpret_cast<float*>(dst + sy[j] - 4) = pv[j].x;
            }
        }
    }
    __syncthreads();

    u64 acc[2][8];
#pragma unroll
    for (int o = 0; o < 2; o++) {
        u64 bb2 = pack2(bz[o], bz[o]);
#pragma unroll
        for (int r = 0; r < 8; r++) acc[o][r] = bb2;
    }

    int buf = 0;
#pragma unroll 1
    for (int ic = 0; ic < IC; ++ic) {
        // prefetch next channel (global loads issued before compute)
        float2 pv[5];
        const bool more = (ic + 1 < IC);
        if (more) {
            const float* plane = inb + (size_t)(ic + 1) * HWPLANE;
#pragma unroll
            for (int j = 0; j < 5; j++)
                pv[j] = (gofs[j] >= 0) ? *reinterpret_cast<const float2*>(plane + gofs[j])
                                       : make_float2(0.0f, 0.0f);
        }

        // weights for this ic into registers
        u64 w[2][9];
        {
            const float2* Wc = &s_w[ic * 36 + half * 18];
#pragma unroll
            for (int ocl = 0; ocl < 2; ocl++)
#pragma unroll
                for (int tap = 0; tap < 9; tap++)
                    w[ocl][tap] = *reinterpret_cast<const u64*>(&Wc[ocl * 9 + tap]);
        }

        const float* S = s_in[buf] + (8 * tY) * 36 + 2 * tX;

        // rolling 3-row window
        u64 p[3][3];
#pragma unroll
        for (int h = 0; h < 3; h++) {
            const float* row = S + h * 36;
            u64 A = *reinterpret_cast<const u64*>(row);
            u64 B = *reinterpret_cast<const u64*>(row + 2);
            float a0, a1, b0, b1;
            unpack2(A, a0, a1); unpack2(B, b0, b1);
            p[h][0] = A; p[h][1] = pack2(a1, b0); p[h][2] = B;
        }

#pragma unroll
        for (int r = 0; r < 8; r++) {
#pragma unroll
            for (int ki = 0; ki < 3; ki++) {
                const int slot = (r + ki) % 3;
#pragma unroll
                for (int kj = 0; kj < 3; kj++) {
                    fma2(acc[0][r], p[slot][kj], w[0][ki * 3 + kj]);
                    fma2(acc[1][r], p[slot][kj], w[1][ki * 3 + kj]);
                }
            }
            if (r < 7) {
                const int slot = r % 3;
                const float* row = S + (r + 3) * 36;
                u64 A = *reinterpret_cast<const u64*>(row);
                u64 B = *reinterpret_cast<const u64*>(row + 2);
                float a0, a1, b0, b1;
                unpack2(A, a0, a1); unpack2(B, b0, b1);
                p[slot][0] = A; p[slot][1] = pack2(a1, b0); p[slot][2] = B;
            }
        }

        // stage next channel into other buffer
        if (more) {
            char* dst = (char*)s_in[buf ^ 1];
#pragma unroll
            for (int j = 0; j < 5; j++) {
                if (sy[j] >= 0) {
                    *reinterpret_cast<float*>(dst + sy[j]) = pv[j].y;
                    if (!((skipx >> j) & 1))
                        *reinterpret_cast<float*>(dst + sy[j] - 4) = pv[j].x;
                }
            }
        }
        __syncthreads();
        buf ^= 1;
    }

    // ---- store ----
    const int x0 = tile_x + 2 * tX;
#pragma unroll
    for (int ocl = 0; ocl < 2; ocl++) {
        int oc = ocA + ocl;
        if (oc >= OC) break;
        size_t base = ((size_t)b * OC + oc) * HWPLANE;
#pragma unroll
        for (int dy = 0; dy < 8; dy++) {
            int y = tile_y + 8 * tY + dy;
            float f0, f1;
            unpack2(acc[ocl][dy], f0, f1);
            size_t idx = base + (size_t)y * WW + x0;
            if (RELU) { f0 = fmaxf(f0, 0.0f); f1 = fmaxf(f1, 0.0f); }
            if (RESID) {
                float2 rv = *reinterpret_cast<const float2*>(resid + idx);
                f0 += rv.x; f1 += rv.y;
            }
            *reinterpret_cast<float2*>(out + idx) = make_float2(f0, f1);
        }
    }
}

// ============================================================
// kernel_conv: softmax(|core|) over 225 taps + dynamic filter
// ============================================================
__global__ __launch_bounds__(256)
void kpn_apply_k(const float* __restrict__ core,
                 const float* __restrict__ data,
                 float* __restrict__ pred)
{
    __shared__ float s_data[3][30][32];

    const int tid = threadIdx.x;
    const int lx = tid & 15;
    const int ly = tid >> 4;
    const int tile_x = blockIdx.x * 16;
    const int tile_y = blockIdx.y * 16;
    const int b = blockIdx.z;

    for (int i = tid; i < 3 * 30 * 30; i += 256) {
        int c = i / 900;
        int r = (i - c * 900) / 30;
        int col = i - c * 900 - r * 30;
        int gy = tile_y - 7 + r;
        int gx = tile_x - 7 + col;
        float v = 0.0f;
        if (gy >= 0 && gy < HH && gx >= 0 && gx < WW)
            v = data[((size_t)b * 3 + c) * HWPLANE + gy * WW + gx];
        s_data[c][r][col] = v;
    }
    __syncthreads();

    const int y = tile_y + ly;
    const int x = tile_x + lx;
    const float* cb = core + (size_t)b * KK2 * HWPLANE + (size_t)y * WW + x;

    float S = 0.0f, P0 = 0.0f, P1 = 0.0f, P2 = 0.0f;

    for (int ki = 0; ki < KK; ki++) {
#pragma unroll
        for (int kj = 0; kj < KK; kj++) {
            float c = cb[(size_t)(ki * KK + kj) * HWPLANE];
            float w = __expf(fabsf(c));
            S += w;
            P0 += w * s_data[0][ly + ki][lx + kj];
            P1 += w * s_data[1][ly + ki][lx + kj];
            P2 += w * s_data[2][ly + ki][lx + kj];
        }
    }

    float inv = 1.0f / S;
    size_t o = (size_t)b * 3 * HWPLANE + (size_t)y * WW + x;
    pred[o]                = P0 * inv;
    pred[o + HWPLANE]      = P1 * inv;
    pred[o + 2 * HWPLANE]  = P2 * inv;
}

static float* sym_addr(const void* s)
{
    void* p = nullptr;
    cudaGetSymbolAddress(&p, s);
    return (float*)p;
}

extern "C" void kernel_launch(void* const* d_in, const int* in_sizes, int n_in,
                              void* d_out, int out_size)
{
    const float* dwe     = (const float*)d_in[0];
    const float* data    = (const float*)d_in[1];
    const float* w_first = (const float*)d_in[2];
    const float* b_first = (const float*)d_in[3];
    const float* w1a = (const float*)d_in[4];
    const float* b1a = (const float*)d_in[5];
    const float* w1b = (const float*)d_in[6];
    const float* b1b = (const float*)d_in[7];
    const float* w2a = (const float*)d_in[8];
    const float* b2a = (const float*)d_in[9];
    const float* w2b = (const float*)d_in[10];
    const float* b2b = (const float*)d_in[11];
    const float* w3a = (const float*)d_in[12];
    const float* b3a = (const float*)d_in[13];
    const float* w3b = (const float*)d_in[14];
    const float* b3b = (const float*)d_in[15];
    const float* w_out = (const float*)d_in[16];
    const float* b_out = (const float*)d_in[17];

    float* f0   = sym_addr(g_feat0);
    float* f1   = sym_addr(g_feat1);
    float* core = sym_addr(g_core);

    dim3 blk(256);
    dim3 grid64(WW / 32, HH / 64, BB * (NF / 4));       // 8,4,64
    const int ocGroupsOut = (KK2 + 3) / 4;              // 57
    dim3 gridOut(WW / 32, HH / 64, BB * ocGroupsOut);   // 8,4,228

    conv3x3_k<6, false, false><<<grid64, blk>>>(dwe, w_first, b_first, nullptr, f0, NF, NF / 4);

    conv3x3_k<64, true,  false><<<grid64, blk>>>(f0, w1a, b1a, nullptr, f1, NF, NF / 4);
    conv3x3_k<64, false, true ><<<grid64, blk>>>(f1, w1b, b1b, f0,      f0, NF, NF / 4);
    conv3x3_k<64, true,  false><<<grid64, blk>>>(f0, w2a, b2a, nullptr, f1, NF, NF / 4);
    conv3x3_k<64, false, true ><<<grid64, blk>>>(f1, w2b, b2b, f0,      f0, NF, NF / 4);
    conv3x3_k<64, true,  false><<<grid64, blk>>>(f0, w3a, b3a, nullptr, f1, NF, NF / 4);
    conv3x3_k<64, false, true ><<<grid64, blk>>>(f1, w3b, b3b, f0,      f0, NF, NF / 4);

    conv3x3_k<64, false, false><<<gridOut, blk>>>(f0, w_out, b_out, nullptr, core, KK2, ocGroupsOut);

    cudaMemcpyAsync(d_out, data, (size_t)BB * 3 * HWPLANE * sizeof(float),
                    cudaMemcpyDeviceToDevice, 0);

    dim3 gridK(WW / 16, HH / 16, BB);
    kpn_apply_k<<<gridK, blk>>>(core, data, (float*)d_out + (size_t)BB * 3 * HWPLANE);
}